// round 13
// baseline (speedup 1.0000x reference)
#include <cuda_runtime.h>
#include <cuda_bf16.h>
#include <cuda_fp16.h>
#include <math.h>
#include <cstdint>

#define BB 32
#define TT 128
#define VV 32000
#define EE 300
#define HH 512
#define G4 (4*HH)      // 2048
#define MM (BB*TT)     // 4096
#define LOGITS_ELEMS ((long long)MM * VV)   // 131072000

// out GEMM: plain fp16, K = 512
#define OKK 512
// xz GEMM: bf16 3-term stacked K
#define XSEG 320
#define XKK (3*XSEG)   // 960

// HMMA GEMM tiling (128x128, BK=64, 256 thr, 3 stages, 2 CTA/SM)
#define OBM 128
#define OBN 128
#define OBK 64
#define OSTAGES 3
#define OTHREADS 256
#define ROWB 144
#define A_ST_BYTES (128*ROWB)
#define B_ST_BYTES (128*ROWB)
#define STAGE_BYTES (A_ST_BYTES + B_ST_BYTES)  // 36864
#define OSMEM (OSTAGES*STAGE_BYTES)            // 110592

// persistent LSTM (HMMA) — byte offsets in dynamic smem
#define NCTA 128
#define RSCALE 2048.0f
#define RINV   (1.0f/2048.0f)
#define SWH_OFF 0                        // fp16 [16][1032]  (Whh | Whl', +8 pad)
#define SWH_ROWB 2064
#define SHH_OFF 33024                    // fp16 [32][520]   hh
#define SH_ROWB 1040
#define SHL_OFF (SHH_OFF + 33280)        // 66304, fp16 [32][520] hl'
#define SZ_OFF  (SHL_OFF + 33280)        // 99584, fp32 [8][16][32]
#define SC_OFF  (SZ_OFF + 16384)         // 115968, fp32 [128]
#define L2SMEM  (SC_OFF + 512)           // 116480 bytes

// ---- scratch (device globals: allocation-free) ----
__device__ float g_xz[MM * G4];        // x @ W_x + b   [4096, 2048]
__device__ float g_xzT[TT * NCTA * 512];  // [t][cta][16][32]
__device__ __half g_hh[2][BB * HH];    // h hi,  [b][u] fp16
__device__ __half g_hl[2][BB * HH];    // h lo * 2048, [b][u] fp16
__device__ __half g_A[(long long)MM * OKK];           // [4096,512]   = Ah
__device__ __half g_B[(long long)VV * OKK];           // [32000,512]  = Bh
__device__ __nv_bfloat16 g_A2[(long long)MM * XKK];   // [4096,960]   = [xh|xl|xh]
__device__ __nv_bfloat16 g_B2[(long long)G4 * XKK];   // [2048,960]   = [Wh|Wh|Wl]
__device__ unsigned g_bar_cnt = 0;
__device__ unsigned g_bar_gen = 0;

// ===========================================================================
__device__ __forceinline__ uint32_t smem_u32(const void* p) {
    uint32_t a;
    asm("{ .reg .u64 t; cvta.to.shared.u64 t, %1; cvt.u32.u64 %0, t; }" : "=r"(a) : "l"(p));
    return a;
}
__device__ __forceinline__ void cp_async16(uint32_t s, const void* g) {
    asm volatile("cp.async.cg.shared.global [%0], [%1], 16;" :: "r"(s), "l"(g));
}
__device__ __forceinline__ void ldm_x4(uint32_t addr, uint32_t* r) {
    asm("ldmatrix.sync.aligned.m8n8.x4.shared.b16 {%0,%1,%2,%3}, [%4];"
        : "=r"(r[0]), "=r"(r[1]), "=r"(r[2]), "=r"(r[3]) : "r"(addr) : "memory");
}
__device__ __forceinline__ void mma_f16(float* d, const uint32_t* a,
                                        uint32_t b0, uint32_t b1) {
    asm("mma.sync.aligned.m16n8k16.row.col.f32.f16.f16.f32 "
        "{%0,%1,%2,%3}, {%4,%5,%6,%7}, {%8,%9}, {%0,%1,%2,%3};"
        : "+f"(d[0]), "+f"(d[1]), "+f"(d[2]), "+f"(d[3])
        : "r"(a[0]), "r"(a[1]), "r"(a[2]), "r"(a[3]), "r"(b0), "r"(b1));
}

// ---------------------------------------------------------------------------
// gather + split: A2[m] = [xh(320) | xl(320) | xh(320)], x = emb[inputs[m]]
// ---------------------------------------------------------------------------
__global__ void split_x_kernel(const int* __restrict__ inputs,
                               const float* __restrict__ emb) {
    int i = blockIdx.x * blockDim.x + threadIdx.x;
    if (i < MM * XSEG) {
        int m = i / XSEG;
        int k = i - m * XSEG;
        float v = (k < EE) ? emb[(long long)inputs[m] * EE + k] : 0.f;
        __nv_bfloat16 hi = __float2bfloat16(v);
        __nv_bfloat16 lo = __float2bfloat16(v - __bfloat162float(hi));
        long long base = (long long)m * XKK;
        g_A2[base + k]            = hi;
        g_A2[base + XSEG + k]     = lo;
        g_A2[base + 2*XSEG + k]   = hi;
    }
}

// ---------------------------------------------------------------------------
// split + transpose W_x [300,2048] -> B2 [2048,960] = [Wh | Wh | Wl]  (bf16)
// ---------------------------------------------------------------------------
__global__ void split_wx_kernel(const float* __restrict__ W) {
    __shared__ float t[32][33];
    int n0 = blockIdx.x * 32, k0 = blockIdx.y * 32;
    int tx = threadIdx.x, ty = threadIdx.y;           // 32 x 8
#pragma unroll
    for (int i = 0; i < 4; i++) {
        int k = k0 + ty + i * 8;
        t[ty + i * 8][tx] = (k < EE) ? W[(long long)k * G4 + n0 + tx] : 0.f;
    }
    __syncthreads();
#pragma unroll
    for (int i = 0; i < 4; i++) {
        int n = ty + i * 8;
        float v = t[tx][n];
        __nv_bfloat16 hi = __float2bfloat16(v);
        __nv_bfloat16 lo = __float2bfloat16(v - __bfloat162float(hi));
        long long base = (long long)(n0 + n) * XKK + k0;
        g_B2[base + tx]            = hi;
        g_B2[base + XSEG + tx]     = hi;
        g_B2[base + 2*XSEG + tx]   = lo;
    }
}

// ---------------------------------------------------------------------------
// transpose + fp16 convert: W_out [512,32000] -> B [32000,512]
// ---------------------------------------------------------------------------
__global__ void split_wout_kernel(const float* __restrict__ W) {
    __shared__ float t[32][33];
    int n0 = blockIdx.x * 32, k0 = blockIdx.y * 32;
    int tx = threadIdx.x, ty = threadIdx.y;   // 32 x 8
#pragma unroll
    for (int i = 0; i < 4; i++) {
        int k = ty + i * 8;
        t[k][tx] = W[(long long)(k0 + k) * VV + n0 + tx];
    }
    __syncthreads();
#pragma unroll
    for (int i = 0; i < 4; i++) {
        int n = ty + i * 8;
        g_B[(long long)(n0 + n) * OKK + k0 + tx] = __float2half(t[tx][n]);
    }
}

// ---------------------------------------------------------------------------
// init h: [b][u] fp16 split pair
// ---------------------------------------------------------------------------
__global__ void init_h_kernel(const float* __restrict__ hidden) {
    int i = blockIdx.x * blockDim.x + threadIdx.x;
    if (i < BB * HH) {
        float v = hidden[i];
        __half hh = __float2half(v);
        g_hh[0][i] = hh;
        g_hl[0][i] = __float2half((v - __half2float(hh)) * RSCALE);
    }
}

// ---------------------------------------------------------------------------
// xz transpose: g_xz [bb*128+t][2048] -> g_xzT [t][c][q=uu*4+g][bb]
// block = (cg, t); reads coalesced 64-float runs, writes coalesced 128B.
// ---------------------------------------------------------------------------
__global__ void xz_transpose_kernel() {
    __shared__ float s[32 * 257];      // s[bb][g*64 + j], pad 1
    const int cg = blockIdx.x;         // 0..7 (16 c's each)
    const int t  = blockIdx.y;         // 0..127
    const int tid = threadIdx.x;       // 256

    // load: thread -> (bb = tid>>3, g = (tid>>1)&3, half = tid&1), 8 x float4
    {
        int bb = tid >> 3, g = (tid >> 1) & 3, half = tid & 1;
        const float* src = g_xz + (long long)(bb * TT + t) * G4 + g * HH
                           + cg * 64 + half * 32;
        float* drow = s + bb * 257 + g * 64 + half * 32;
#pragma unroll
        for (int i = 0; i < 8; i++) {
            float4 v = *(const float4*)(src + i * 4);
            drow[i * 4 + 0] = v.x; drow[i * 4 + 1] = v.y;
            drow[i * 4 + 2] = v.z; drow[i * 4 + 3] = v.w;
        }
    }
    __syncthreads();
    // write: idx -> (bb, q, cl); consecutive tid -> consecutive bb (coalesced)
    const long long outbase = ((long long)t * NCTA + cg * 16) * 512;
#pragma unroll
    for (int w = 0; w < 32; w++) {
        int idx = w * 256 + tid;
        int bb = idx & 31, q = (idx >> 5) & 15, cl = idx >> 9;
        int g = q & 3, uu = q >> 2;
        g_xzT[outbase + (cl * 16 + q) * 32 + bb] = s[bb * 257 + g * 64 + cl * 4 + uu];
    }
}

// ---------------------------------------------------------------------------
// Generic HMMA 16-bit GEMM (unchanged)
// ---------------------------------------------------------------------------
template<int FP16M>
__global__ void __launch_bounds__(OTHREADS, 2)
hmma_gemm(const uint16_t* __restrict__ A, const uint16_t* __restrict__ B,
          const float* __restrict__ bias, float* __restrict__ C,
          int N, int K) {
    extern __shared__ char smem[];
    const int tid  = threadIdx.x;
    const int lane = tid & 31;
    const int wid  = tid >> 5;
    const int wm   = wid & 3;
    const int wn   = wid >> 2;
    const int m0 = blockIdx.x * OBM;
    const int n0 = blockIdx.y * OBN;
    const uint32_t sbase = smem_u32(smem);

    auto load_stage = [&](int s, int kt) {
        uint32_t sA = sbase + s * STAGE_BYTES;
        uint32_t sB = sA + A_ST_BYTES;
        long long k0 = (long long)kt * OBK;
#pragma unroll
        for (int i = 0; i < 4; i++) {
            int idx = tid + i * 256;
            int r = idx >> 3, ch = idx & 7;
            cp_async16(sA + r * ROWB + ch * 16,
                       A + (long long)(m0 + r) * K + k0 + ch * 8);
        }
#pragma unroll
        for (int i = 0; i < 4; i++) {
            int idx = tid + i * 256;
            int r = idx >> 3, ch = idx & 7;
            cp_async16(sB + r * ROWB + ch * 16,
                       B + (long long)(n0 + r) * K + k0 + ch * 8);
        }
        asm volatile("cp.async.commit_group;" ::: "memory");
    };

    float acc[2][8][4];
#pragma unroll
    for (int i = 0; i < 2; i++)
#pragma unroll
        for (int j = 0; j < 8; j++)
#pragma unroll
            for (int q = 0; q < 4; q++) acc[i][j][q] = 0.f;

    const int KT = K / OBK;
#pragma unroll
    for (int s = 0; s < OSTAGES - 1; s++)
        if (s < KT) load_stage(s, s);

    for (int kt = 0; kt < KT; kt++) {
        asm volatile("cp.async.wait_group %0;" :: "n"(OSTAGES - 2));
        __syncthreads();
        if (kt + OSTAGES - 1 < KT)
            load_stage((kt + OSTAGES - 1) % OSTAGES, kt + OSTAGES - 1);

        uint32_t sA = sbase + (kt % OSTAGES) * STAGE_BYTES;
        uint32_t sB = sA + A_ST_BYTES;
        const int krow = lane & 15;
#pragma unroll
        for (int ks = 0; ks < 4; ks++) {
            const int kcolb = (ks * 16 + (lane >> 4) * 8) * 2;
            uint32_t a[2][4], bb[4][4];
#pragma unroll
            for (int mt = 0; mt < 2; mt++)
                ldm_x4(sA + (wm * 32 + mt * 16 + krow) * ROWB + kcolb, a[mt]);
#pragma unroll
            for (int np = 0; np < 4; np++)
                ldm_x4(sB + (wn * 64 + np * 16 + krow) * ROWB + kcolb, bb[np]);
#pragma unroll
            for (int mt = 0; mt < 2; mt++)
#pragma unroll
                for (int nt = 0; nt < 8; nt++) {
                    uint32_t b0 = bb[nt >> 1][nt & 1];
                    uint32_t b1 = bb[nt >> 1][(nt & 1) + 2];
                    if (FP16M) {
                        mma_f16(acc[mt][nt], a[mt], b0, b1);
                    } else {
                        asm("mma.sync.aligned.m16n8k16.row.col.f32.bf16.bf16.f32 "
                            "{%0,%1,%2,%3}, {%4,%5,%6,%7}, {%8,%9}, {%0,%1,%2,%3};"
                            : "+f"(acc[mt][nt][0]), "+f"(acc[mt][nt][1]),
                              "+f"(acc[mt][nt][2]), "+f"(acc[mt][nt][3])
                            : "r"(a[mt][0]), "r"(a[mt][1]), "r"(a[mt][2]), "r"(a[mt][3]),
                              "r"(b0), "r"(b1));
                    }
                }
        }
    }

    const int row_b = m0 + wm * 32 + (lane >> 2);
    const int col_b = n0 + wn * 64 + (lane & 3) * 2;
#pragma unroll
    for (int nt = 0; nt < 8; nt++) {
        int col = col_b + nt * 8;
        float b0v = __ldg(bias + col);
        float b1v = __ldg(bias + col + 1);
#pragma unroll
        for (int mt = 0; mt < 2; mt++) {
            long long r0 = row_b + mt * 16;
            float2 v0 = make_float2(acc[mt][nt][0] + b0v, acc[mt][nt][1] + b1v);
            float2 v1 = make_float2(acc[mt][nt][2] + b0v, acc[mt][nt][3] + b1v);
            *(float2*)&C[r0 * N + col]       = v0;
            *(float2*)&C[(r0 + 8) * N + col] = v1;
        }
    }
}

// ---------------------------------------------------------------------------
// Persistent LSTM, HMMA matvec + xzT register prefetch + acq/rel barrier
// ---------------------------------------------------------------------------
__global__ void __launch_bounds__(256, 1)
lstm_persistent(const float* __restrict__ Wh, const float* __restrict__ cell,
                float* __restrict__ out) {
    extern __shared__ char smem[];
    float* sz = (float*)(smem + SZ_OFF);
    float* sc = (float*)(smem + SC_OFF);
    const uint32_t sbase = smem_u32(smem);
    const int tid = threadIdx.x;
    const int lane = tid & 31;
    const int kg = tid >> 5;           // warp id = K group
    const int u0 = blockIdx.x * 4;

    __shared__ unsigned s_gen0;
    if (tid == 0) {
        unsigned g0;
        asm volatile("ld.acquire.gpu.global.u32 %0, [%1];"
                     : "=r"(g0) : "l"(&g_bar_gen) : "memory");
        s_gen0 = g0;
    }

    // one-time: Wh slice -> fp16 2-term in smem
#pragma unroll
    for (int it = 0; it < 32; it++) {
        int e = tid + it * 256;        // 0..8191
        int k = e >> 4, c = e & 15;
        int uu = c >> 2, g = c & 3;
        float w = Wh[(long long)k * G4 + g * HH + u0 + uu];
        __half wh = __float2half(w);
        __half wl = __float2half((w - __half2float(wh)) * RSCALE);
        *(__half*)(smem + SWH_OFF + c * SWH_ROWB + k * 2)         = wh;
        *(__half*)(smem + SWH_OFF + c * SWH_ROWB + (512 + k) * 2) = wl;
    }
    if (tid < 128) sc[tid] = cell[(tid & 31) * HH + u0 + (tid >> 5)];
    __syncthreads();
    const unsigned gen0 = s_gen0;

    for (int t = 0; t < TT; t++) {
        const __half* __restrict__ srch = g_hh[t & 1];
        const __half* __restrict__ srcl = g_hl[t & 1];

        // warp loads its K slice of hh and hl'
#pragma unroll
        for (int j = 0; j < 8; j++) {
            int e = lane + j * 32;
            int b = e >> 3, ch = e & 7;
            cp_async16(sbase + SHH_OFF + b * SH_ROWB + kg * 128 + ch * 16,
                       srch + b * HH + kg * 64 + ch * 8);
            cp_async16(sbase + SHL_OFF + b * SH_ROWB + kg * 128 + ch * 16,
                       srcl + b * HH + kg * 64 + ch * 8);
        }
        asm volatile("cp.async.commit_group;" ::: "memory");

        // xz prefetch (contiguous 2KB per CTA per step; hides under wait+mma)
        float xzv[4];
        if (tid < 128) {
            const float* p = g_xzT + ((long long)t * NCTA + blockIdx.x) * 512;
            int bb = tid & 31, uu = tid >> 5;
#pragma unroll
            for (int g = 0; g < 4; g++)
                xzv[g] = __ldg(p + uu * 128 + g * 32 + bb);
        }

        asm volatile("cp.async.wait_group 0;" ::: "memory");
        __syncwarp();

        // HMMA: accA = hh*Whh ; accB = hl'*Whh + hh*Whl'
        float accA[2][2][4], accB[2][2][4];
#pragma unroll
        for (int i = 0; i < 2; i++)
#pragma unroll
            for (int j = 0; j < 2; j++)
#pragma unroll
                for (int q = 0; q < 4; q++) { accA[i][j][q] = 0.f; accB[i][j][q] = 0.f; }

        const int krow = lane & 15;
        const int kgrp = (lane >> 4) * 8;
#pragma unroll
        for (int seg = 0; seg < 3; seg++) {
            const uint32_t Abase = sbase + ((seg == 1) ? SHL_OFF : SHH_OFF);
            const uint32_t Bkoff = (seg == 2) ? 512u : 0u;
            float (*acc)[2][4] = (seg == 0) ? accA : accB;
#pragma unroll
            for (int ki = 0; ki < 4; ki++) {
                const int kcol = kg * 64 + ki * 16;
                uint32_t a[2][4], bb[4];
#pragma unroll
                for (int mt = 0; mt < 2; mt++)
                    ldm_x4(Abase + (mt * 16 + krow) * SH_ROWB + (kcol + kgrp) * 2, a[mt]);
                ldm_x4(sbase + SWH_OFF + krow * SWH_ROWB + (Bkoff + kcol + kgrp) * 2, bb);
#pragma unroll
                for (int mt = 0; mt < 2; mt++)
#pragma unroll
                    for (int nt = 0; nt < 2; nt++)
                        mma_f16(acc[mt][nt], a[mt], bb[nt], bb[nt + 2]);
            }
        }

        // partials -> sz[kg][c][b]
        {
            float* zb = sz + kg * 512;
#pragma unroll
            for (int mt = 0; mt < 2; mt++)
#pragma unroll
                for (int nt = 0; nt < 2; nt++)
#pragma unroll
                    for (int q = 0; q < 4; q++) {
                        int b = mt * 16 + (lane >> 2) + ((q >> 1) * 8);
                        int c = nt * 8 + (lane & 3) * 2 + (q & 1);
                        zb[c * 32 + b] = accA[mt][nt][q] + accB[mt][nt][q] * RINV;
                    }
        }
        __syncthreads();

        // reduce partials + nonlinearity (128 threads: 32 b x 4 units)
        if (tid < 128) {
            int bb = tid & 31, uu = tid >> 5;
            float z[4];
#pragma unroll
            for (int g = 0; g < 4; g++) {
                int c = uu * 4 + g;
                float s = 0.f;
#pragma unroll
                for (int q = 0; q < 8; q++) s += sz[q * 512 + c * 32 + bb];
                z[g] = s;
            }
            float zi = z[0] + xzv[0];
            float zf = z[1] + xzv[1];
            float zg = z[2] + xzv[2];
            float zo = z[3] + xzv[3];
            float si = 1.f / (1.f + expf(-zi));
            float sf = 1.f / (1.f + expf(-zf));
            float so = 1.f / (1.f + expf(-zo));
            float cn = sf * sc[tid] + si * tanhf(zg);
            float hn = so * tanhf(cn);
            sc[tid] = cn;
            __half hh = __float2half(hn);
            __half hl = __float2half((hn - __half2float(hh)) * RSCALE);
            int hidx = bb * HH + u0 + uu;
            g_hh[(t + 1) & 1][hidx] = hh;
            g_hl[(t + 1) & 1][hidx] = hl;
            g_A[(long long)(bb * TT + t) * OKK + u0 + uu] = hh;
            if (t == TT - 1)
                out[LOGITS_ELEMS + hidx] = hn;
        }

        // grid barrier (release arrival / acquire poll; no full fences)
        __syncthreads();
        if (tid == 0) {
            unsigned old;
            asm volatile("atom.release.gpu.global.add.u32 %0, [%1], %2;"
                         : "=r"(old) : "l"(&g_bar_cnt), "r"(1u) : "memory");
            if (old == NCTA - 1) {
                asm volatile("st.relaxed.gpu.global.u32 [%0], %1;"
                             :: "l"(&g_bar_cnt), "r"(0u) : "memory");
                unsigned d;
                asm volatile("atom.release.gpu.global.add.u32 %0, [%1], %2;"
                             : "=r"(d) : "l"(&g_bar_gen), "r"(1u) : "memory");
            } else {
                unsigned g;
                do {
                    asm volatile("ld.acquire.gpu.global.u32 %0, [%1];"
                                 : "=r"(g) : "l"(&g_bar_gen) : "memory");
                } while (g - gen0 < (unsigned)(t + 1));
            }
        }
        __syncthreads();
    }

    if (tid < 128) {
        out[LOGITS_ELEMS + BB * HH + (tid & 31) * HH + u0 + (tid >> 5)] = sc[tid];
    }
}

// ---------------------------------------------------------------------------
extern "C" void kernel_launch(void* const* d_in, const int* in_sizes, int n_in,
                              void* d_out, int out_size) {
    const int*   inputs = (const int*)  d_in[0];
    const float* hidden = (const float*)d_in[1];
    const float* cell   = (const float*)d_in[2];
    const float* emb    = (const float*)d_in[3];
    const float* Wx     = (const float*)d_in[4];
    const float* Wh     = (const float*)d_in[5];
    const float* bias   = (const float*)d_in[6];
    const float* Wout   = (const float*)d_in[7];
    const float* bout   = (const float*)d_in[8];
    float* out = (float*)d_out;

    float *pxz;
    __half *pA, *pB;
    __nv_bfloat16 *pA2, *pB2;
    cudaGetSymbolAddress((void**)&pxz, g_xz);
    cudaGetSymbolAddress((void**)&pA,  g_A);
    cudaGetSymbolAddress((void**)&pB,  g_B);
    cudaGetSymbolAddress((void**)&pA2, g_A2);
    cudaGetSymbolAddress((void**)&pB2, g_B2);

    cudaFuncSetAttribute(hmma_gemm<0>,
                         cudaFuncAttributeMaxDynamicSharedMemorySize, OSMEM);
    cudaFuncSetAttribute(hmma_gemm<1>,
                         cudaFuncAttributeMaxDynamicSharedMemorySize, OSMEM);
    cudaFuncSetAttribute(lstm_persistent,
                         cudaFuncAttributeMaxDynamicSharedMemorySize, L2SMEM);

    // 1. gather + split x -> A2 (bf16 3-term)
    split_x_kernel<<<(MM * XSEG + 255) / 256, 256>>>(inputs, emb);

    // 2. split + transpose W_x -> B2 (bf16 3-term)
    {
        dim3 grid(G4 / 32, XSEG / 32);   // (64, 10)
        split_wx_kernel<<<grid, dim3(32, 8)>>>(Wx);
    }

    // 3. init h (fp16 split pair)
    init_h_kernel<<<(BB * HH + 255) / 256, 256>>>(hidden);

    // 4. xz = A2 @ B2^T + b  (bf16 HMMA, 4096 x 2048 x 960)
    {
        dim3 grid(MM / OBM, G4 / OBN);   // (32, 16)
        hmma_gemm<0><<<grid, OTHREADS, OSMEM>>>((const uint16_t*)pA2,
                                                (const uint16_t*)pB2,
                                                bias, pxz, G4, XKK);
    }

    // 5. transpose xz -> per-(t, cta) contiguous layout
    {
        dim3 grid(8, TT);               // (cg, t)
        xz_transpose_kernel<<<grid, 256>>>();
    }

    // 6. transpose W_out -> B (fp16)
    {
        dim3 grid(VV / 32, HH / 32);
        split_wout_kernel<<<grid, dim3(32, 8)>>>(Wout);
    }

    // 7. all 128 LSTM steps in ONE persistent launch (HMMA matvec)
    lstm_persistent<<<NCTA, 256, L2SMEM>>>(Wh, cell, out);

    // 8. logits = A @ B^T + b_out  (fp16 HMMA, 4096 x 32000 x 512)
    {
        dim3 grid(MM / OBM, VV / OBN);   // (32, 250)
        hmma_gemm<1><<<grid, OTHREADS, OSMEM>>>((const uint16_t*)pA,
                                                (const uint16_t*)pB,
                                                bout, out, VV, OKK);
    }
}

// round 14
// speedup vs baseline: 1.3889x; 1.3889x over previous
#include <cuda_runtime.h>
#include <cuda_bf16.h>
#include <cuda_fp16.h>
#include <math.h>
#include <cstdint>

#define BB 32
#define TT 128
#define VV 32000
#define EE 300
#define HH 512
#define G4 (4*HH)      // 2048
#define MM (BB*TT)     // 4096
#define LOGITS_ELEMS ((long long)MM * VV)   // 131072000

// out GEMM: plain fp16, K = 512
#define OKK 512
// xz GEMM: bf16 3-term stacked K
#define XSEG 320
#define XKK (3*XSEG)   // 960

// HMMA GEMM tiling (128x128, BK=64, 256 thr, 3 stages, 2 CTA/SM)
#define OBM 128
#define OBN 128
#define OBK 64
#define OSTAGES 3
#define OTHREADS 256
#define ROWB 144
#define A_ST_BYTES (128*ROWB)
#define B_ST_BYTES (128*ROWB)
#define STAGE_BYTES (A_ST_BYTES + B_ST_BYTES)  // 36864
#define OSMEM (OSTAGES*STAGE_BYTES)            // 110592

// persistent LSTM (HMMA) — byte offsets in dynamic smem
#define NCTA 128
#define RSCALE 2048.0f
#define RINV   (1.0f/2048.0f)
#define SWH_OFF 0                        // fp16 [16][1032]  (Whh | Whl', +8 pad)
#define SWH_ROWB 2064
#define SHH_OFF 33024                    // fp16 [32][520]   hh
#define SH_ROWB 1040
#define SHL_OFF (SHH_OFF + 33280)        // 66304, fp16 [32][520] hl'
#define SZ_OFF  (SHL_OFF + 33280)        // 99584, fp32 [8][16][32]
#define SC_OFF  (SZ_OFF + 16384)         // 115968, fp32 [128]
#define L2SMEM  (SC_OFF + 512)           // 116480 bytes

// ---- scratch (device globals: allocation-free) ----
__device__ float g_xz[MM * G4];        // x @ W_x + b   [4096, 2048]
__device__ __half g_hh[2][BB * HH];    // h hi,  [b][u] fp16
__device__ __half g_hl[2][BB * HH];    // h lo * 2048, [b][u] fp16
__device__ __half g_A[(long long)MM * OKK];           // [4096,512]   = Ah
__device__ __half g_B[(long long)VV * OKK];           // [32000,512]  = Bh
__device__ __nv_bfloat16 g_A2[(long long)MM * XKK];   // [4096,960]   = [xh|xl|xh]
__device__ __nv_bfloat16 g_B2[(long long)G4 * XKK];   // [2048,960]   = [Wh|Wh|Wl]
__device__ unsigned g_bar_cnt = 0;
__device__ unsigned g_bar_gen = 0;

// ===========================================================================
__device__ __forceinline__ uint32_t smem_u32(const void* p) {
    uint32_t a;
    asm("{ .reg .u64 t; cvta.to.shared.u64 t, %1; cvt.u32.u64 %0, t; }" : "=r"(a) : "l"(p));
    return a;
}
__device__ __forceinline__ void cp_async16(uint32_t s, const void* g) {
    asm volatile("cp.async.cg.shared.global [%0], [%1], 16;" :: "r"(s), "l"(g));
}
__device__ __forceinline__ void ldm_x4(uint32_t addr, uint32_t* r) {
    asm("ldmatrix.sync.aligned.m8n8.x4.shared.b16 {%0,%1,%2,%3}, [%4];"
        : "=r"(r[0]), "=r"(r[1]), "=r"(r[2]), "=r"(r[3]) : "r"(addr) : "memory");
}
__device__ __forceinline__ void mma_f16(float* d, const uint32_t* a,
                                        uint32_t b0, uint32_t b1) {
    asm("mma.sync.aligned.m16n8k16.row.col.f32.f16.f16.f32 "
        "{%0,%1,%2,%3}, {%4,%5,%6,%7}, {%8,%9}, {%0,%1,%2,%3};"
        : "+f"(d[0]), "+f"(d[1]), "+f"(d[2]), "+f"(d[3])
        : "r"(a[0]), "r"(a[1]), "r"(a[2]), "r"(a[3]), "r"(b0), "r"(b1));
}

// ---------------------------------------------------------------------------
// gather + split: A2[m] = [xh(320) | xl(320) | xh(320)], x = emb[inputs[m]]
// ---------------------------------------------------------------------------
__global__ void split_x_kernel(const int* __restrict__ inputs,
                               const float* __restrict__ emb) {
    int i = blockIdx.x * blockDim.x + threadIdx.x;
    if (i < MM * XSEG) {
        int m = i / XSEG;
        int k = i - m * XSEG;
        float v = (k < EE) ? emb[(long long)inputs[m] * EE + k] : 0.f;
        __nv_bfloat16 hi = __float2bfloat16(v);
        __nv_bfloat16 lo = __float2bfloat16(v - __bfloat162float(hi));
        long long base = (long long)m * XKK;
        g_A2[base + k]            = hi;
        g_A2[base + XSEG + k]     = lo;
        g_A2[base + 2*XSEG + k]   = hi;
    }
}

// ---------------------------------------------------------------------------
// split + transpose W_x [300,2048] -> B2 [2048,960] = [Wh | Wh | Wl]  (bf16)
// ---------------------------------------------------------------------------
__global__ void split_wx_kernel(const float* __restrict__ W) {
    __shared__ float t[32][33];
    int n0 = blockIdx.x * 32, k0 = blockIdx.y * 32;
    int tx = threadIdx.x, ty = threadIdx.y;           // 32 x 8
#pragma unroll
    for (int i = 0; i < 4; i++) {
        int k = k0 + ty + i * 8;
        t[ty + i * 8][tx] = (k < EE) ? W[(long long)k * G4 + n0 + tx] : 0.f;
    }
    __syncthreads();
#pragma unroll
    for (int i = 0; i < 4; i++) {
        int n = ty + i * 8;
        float v = t[tx][n];
        __nv_bfloat16 hi = __float2bfloat16(v);
        __nv_bfloat16 lo = __float2bfloat16(v - __bfloat162float(hi));
        long long base = (long long)(n0 + n) * XKK + k0;
        g_B2[base + tx]            = hi;
        g_B2[base + XSEG + tx]     = hi;
        g_B2[base + 2*XSEG + tx]   = lo;
    }
}

// ---------------------------------------------------------------------------
// transpose + fp16 convert: W_out [512,32000] -> B [32000,512]
// ---------------------------------------------------------------------------
__global__ void split_wout_kernel(const float* __restrict__ W) {
    __shared__ float t[32][33];
    int n0 = blockIdx.x * 32, k0 = blockIdx.y * 32;
    int tx = threadIdx.x, ty = threadIdx.y;   // 32 x 8
#pragma unroll
    for (int i = 0; i < 4; i++) {
        int k = ty + i * 8;
        t[k][tx] = W[(long long)(k0 + k) * VV + n0 + tx];
    }
    __syncthreads();
#pragma unroll
    for (int i = 0; i < 4; i++) {
        int n = ty + i * 8;
        g_B[(long long)(n0 + n) * OKK + k0 + tx] = __float2half(t[tx][n]);
    }
}

// ---------------------------------------------------------------------------
// init h: [b][u] fp16 split pair
// ---------------------------------------------------------------------------
__global__ void init_h_kernel(const float* __restrict__ hidden) {
    int i = blockIdx.x * blockDim.x + threadIdx.x;
    if (i < BB * HH) {
        float v = hidden[i];
        __half hh = __float2half(v);
        g_hh[0][i] = hh;
        g_hl[0][i] = __float2half((v - __half2float(hh)) * RSCALE);
    }
}

// ---------------------------------------------------------------------------
// Generic HMMA 16-bit GEMM (unchanged)
// ---------------------------------------------------------------------------
template<int FP16M>
__global__ void __launch_bounds__(OTHREADS, 2)
hmma_gemm(const uint16_t* __restrict__ A, const uint16_t* __restrict__ B,
          const float* __restrict__ bias, float* __restrict__ C,
          int N, int K) {
    extern __shared__ char smem[];
    const int tid  = threadIdx.x;
    const int lane = tid & 31;
    const int wid  = tid >> 5;
    const int wm   = wid & 3;
    const int wn   = wid >> 2;
    const int m0 = blockIdx.x * OBM;
    const int n0 = blockIdx.y * OBN;
    const uint32_t sbase = smem_u32(smem);

    auto load_stage = [&](int s, int kt) {
        uint32_t sA = sbase + s * STAGE_BYTES;
        uint32_t sB = sA + A_ST_BYTES;
        long long k0 = (long long)kt * OBK;
#pragma unroll
        for (int i = 0; i < 4; i++) {
            int idx = tid + i * 256;
            int r = idx >> 3, ch = idx & 7;
            cp_async16(sA + r * ROWB + ch * 16,
                       A + (long long)(m0 + r) * K + k0 + ch * 8);
        }
#pragma unroll
        for (int i = 0; i < 4; i++) {
            int idx = tid + i * 256;
            int r = idx >> 3, ch = idx & 7;
            cp_async16(sB + r * ROWB + ch * 16,
                       B + (long long)(n0 + r) * K + k0 + ch * 8);
        }
        asm volatile("cp.async.commit_group;" ::: "memory");
    };

    float acc[2][8][4];
#pragma unroll
    for (int i = 0; i < 2; i++)
#pragma unroll
        for (int j = 0; j < 8; j++)
#pragma unroll
            for (int q = 0; q < 4; q++) acc[i][j][q] = 0.f;

    const int KT = K / OBK;
#pragma unroll
    for (int s = 0; s < OSTAGES - 1; s++)
        if (s < KT) load_stage(s, s);

    for (int kt = 0; kt < KT; kt++) {
        asm volatile("cp.async.wait_group %0;" :: "n"(OSTAGES - 2));
        __syncthreads();
        if (kt + OSTAGES - 1 < KT)
            load_stage((kt + OSTAGES - 1) % OSTAGES, kt + OSTAGES - 1);

        uint32_t sA = sbase + (kt % OSTAGES) * STAGE_BYTES;
        uint32_t sB = sA + A_ST_BYTES;
        const int krow = lane & 15;
#pragma unroll
        for (int ks = 0; ks < 4; ks++) {
            const int kcolb = (ks * 16 + (lane >> 4) * 8) * 2;
            uint32_t a[2][4], bb[4][4];
#pragma unroll
            for (int mt = 0; mt < 2; mt++)
                ldm_x4(sA + (wm * 32 + mt * 16 + krow) * ROWB + kcolb, a[mt]);
#pragma unroll
            for (int np = 0; np < 4; np++)
                ldm_x4(sB + (wn * 64 + np * 16 + krow) * ROWB + kcolb, bb[np]);
#pragma unroll
            for (int mt = 0; mt < 2; mt++)
#pragma unroll
                for (int nt = 0; nt < 8; nt++) {
                    uint32_t b0 = bb[nt >> 1][nt & 1];
                    uint32_t b1 = bb[nt >> 1][(nt & 1) + 2];
                    if (FP16M) {
                        mma_f16(acc[mt][nt], a[mt], b0, b1);
                    } else {
                        asm("mma.sync.aligned.m16n8k16.row.col.f32.bf16.bf16.f32 "
                            "{%0,%1,%2,%3}, {%4,%5,%6,%7}, {%8,%9}, {%0,%1,%2,%3};"
                            : "+f"(acc[mt][nt][0]), "+f"(acc[mt][nt][1]),
                              "+f"(acc[mt][nt][2]), "+f"(acc[mt][nt][3])
                            : "r"(a[mt][0]), "r"(a[mt][1]), "r"(a[mt][2]), "r"(a[mt][3]),
                              "r"(b0), "r"(b1));
                    }
                }
        }
    }

    const int row_b = m0 + wm * 32 + (lane >> 2);
    const int col_b = n0 + wn * 64 + (lane & 3) * 2;
#pragma unroll
    for (int nt = 0; nt < 8; nt++) {
        int col = col_b + nt * 8;
        float b0v = __ldg(bias + col);
        float b1v = __ldg(bias + col + 1);
#pragma unroll
        for (int mt = 0; mt < 2; mt++) {
            long long r0 = row_b + mt * 16;
            float2 v0 = make_float2(acc[mt][nt][0] + b0v, acc[mt][nt][1] + b1v);
            float2 v1 = make_float2(acc[mt][nt][2] + b0v, acc[mt][nt][3] + b1v);
            *(float2*)&C[r0 * N + col]       = v0;
            *(float2*)&C[(r0 + 8) * N + col] = v1;
        }
    }
}

// ---------------------------------------------------------------------------
// Persistent LSTM, HMMA matvec (R12 structure + early xz register prefetch)
// ---------------------------------------------------------------------------
__global__ void __launch_bounds__(256, 1)
lstm_persistent(const float* __restrict__ Wh, const float* __restrict__ cell,
                float* __restrict__ out) {
    extern __shared__ char smem[];
    float* sz = (float*)(smem + SZ_OFF);
    float* sc = (float*)(smem + SC_OFF);
    const uint32_t sbase = smem_u32(smem);
    const int tid = threadIdx.x;
    const int lane = tid & 31;
    const int kg = tid >> 5;           // warp id = K group
    const int u0 = blockIdx.x * 4;

    __shared__ unsigned s_gen0;
    if (tid == 0) s_gen0 = *(volatile unsigned*)&g_bar_gen;

    // one-time: Wh slice -> fp16 2-term in smem
#pragma unroll
    for (int it = 0; it < 32; it++) {
        int e = tid + it * 256;        // 0..8191
        int k = e >> 4, c = e & 15;
        int uu = c >> 2, g = c & 3;
        float w = Wh[(long long)k * G4 + g * HH + u0 + uu];
        __half wh = __float2half(w);
        __half wl = __float2half((w - __half2float(wh)) * RSCALE);
        *(__half*)(smem + SWH_OFF + c * SWH_ROWB + k * 2)         = wh;
        *(__half*)(smem + SWH_OFF + c * SWH_ROWB + (512 + k) * 2) = wl;
    }
    if (tid < 128) sc[tid] = cell[(tid & 31) * HH + u0 + (tid >> 5)];
    __syncthreads();
    const unsigned gen0 = s_gen0;

    for (int t = 0; t < TT; t++) {
        const __half* __restrict__ srch = g_hh[t & 1];
        const __half* __restrict__ srcl = g_hl[t & 1];

        // warp loads its K slice of hh and hl'
#pragma unroll
        for (int j = 0; j < 8; j++) {
            int e = lane + j * 32;
            int b = e >> 3, ch = e & 7;
            cp_async16(sbase + SHH_OFF + b * SH_ROWB + kg * 128 + ch * 16,
                       srch + b * HH + kg * 64 + ch * 8);
            cp_async16(sbase + SHL_OFF + b * SH_ROWB + kg * 128 + ch * 16,
                       srcl + b * HH + kg * 64 + ch * 8);
        }
        asm volatile("cp.async.commit_group;" ::: "memory");

        // early xz prefetch into registers (same addresses as R12's gather,
        // issued here so L2 latency hides under the h-wait + MMA)
        float xzv[4];
        if (tid < 128) {
            int bb = tid & 31, uu = tid >> 5;
            const float* xzr = g_xz + (long long)(bb * TT + t) * G4 + u0 + uu;
            xzv[0] = __ldg(xzr);
            xzv[1] = __ldg(xzr + HH);
            xzv[2] = __ldg(xzr + 2 * HH);
            xzv[3] = __ldg(xzr + 3 * HH);
        }

        asm volatile("cp.async.wait_group 0;" ::: "memory");
        __syncwarp();

        // HMMA: accA = hh*Whh ; accB = hl'*Whh + hh*Whl'
        float accA[2][2][4], accB[2][2][4];
#pragma unroll
        for (int i = 0; i < 2; i++)
#pragma unroll
            for (int j = 0; j < 2; j++)
#pragma unroll
                for (int q = 0; q < 4; q++) { accA[i][j][q] = 0.f; accB[i][j][q] = 0.f; }

        const int krow = lane & 15;
        const int kgrp = (lane >> 4) * 8;
#pragma unroll
        for (int seg = 0; seg < 3; seg++) {
            const uint32_t Abase = sbase + ((seg == 1) ? SHL_OFF : SHH_OFF);
            const uint32_t Bkoff = (seg == 2) ? 512u : 0u;
            float (*acc)[2][4] = (seg == 0) ? accA : accB;
#pragma unroll
            for (int ki = 0; ki < 4; ki++) {
                const int kcol = kg * 64 + ki * 16;
                uint32_t a[2][4], bb[4];
#pragma unroll
                for (int mt = 0; mt < 2; mt++)
                    ldm_x4(Abase + (mt * 16 + krow) * SH_ROWB + (kcol + kgrp) * 2, a[mt]);
                ldm_x4(sbase + SWH_OFF + krow * SWH_ROWB + (Bkoff + kcol + kgrp) * 2, bb);
#pragma unroll
                for (int mt = 0; mt < 2; mt++)
#pragma unroll
                    for (int nt = 0; nt < 2; nt++)
                        mma_f16(acc[mt][nt], a[mt], bb[nt], bb[nt + 2]);
            }
        }

        // partials -> sz[kg][c][b]
        {
            float* zb = sz + kg * 512;
#pragma unroll
            for (int mt = 0; mt < 2; mt++)
#pragma unroll
                for (int nt = 0; nt < 2; nt++)
#pragma unroll
                    for (int q = 0; q < 4; q++) {
                        int b = mt * 16 + (lane >> 2) + ((q >> 1) * 8);
                        int c = nt * 8 + (lane & 3) * 2 + (q & 1);
                        zb[c * 32 + b] = accA[mt][nt][q] + accB[mt][nt][q] * RINV;
                    }
        }
        __syncthreads();

        // reduce partials + nonlinearity (128 threads: 32 b x 4 units)
        if (tid < 128) {
            int bb = tid & 31, uu = tid >> 5;
            float z[4];
#pragma unroll
            for (int g = 0; g < 4; g++) {
                int c = uu * 4 + g;
                float s = 0.f;
#pragma unroll
                for (int q = 0; q < 8; q++) s += sz[q * 512 + c * 32 + bb];
                z[g] = s;
            }
            float zi = z[0] + xzv[0];
            float zf = z[1] + xzv[1];
            float zg = z[2] + xzv[2];
            float zo = z[3] + xzv[3];
            float si = 1.f / (1.f + expf(-zi));
            float sf = 1.f / (1.f + expf(-zf));
            float so = 1.f / (1.f + expf(-zo));
            float cn = sf * sc[tid] + si * tanhf(zg);
            float hn = so * tanhf(cn);
            sc[tid] = cn;
            __half hh = __float2half(hn);
            __half hl = __float2half((hn - __half2float(hh)) * RSCALE);
            int hidx = bb * HH + u0 + uu;
            g_hh[(t + 1) & 1][hidx] = hh;
            g_hl[(t + 1) & 1][hidx] = hl;
            g_A[(long long)(bb * TT + t) * OKK + u0 + uu] = hh;
            if (t == TT - 1)
                out[LOGITS_ELEMS + hidx] = hn;
        }

        // grid barrier (R12 proven version)
        __syncthreads();
        if (tid == 0) {
            __threadfence();
            if (atomicAdd(&g_bar_cnt, 1u) == NCTA - 1) {
                *(volatile unsigned*)&g_bar_cnt = 0;
                __threadfence();
                atomicAdd(&g_bar_gen, 1u);
            } else {
                while (*(volatile unsigned*)&g_bar_gen - gen0 < (unsigned)(t + 1)) { }
            }
            __threadfence();
        }
        __syncthreads();
    }

    if (tid < 128) {
        out[LOGITS_ELEMS + BB * HH + (tid & 31) * HH + u0 + (tid >> 5)] = sc[tid];
    }
}

// ---------------------------------------------------------------------------
extern "C" void kernel_launch(void* const* d_in, const int* in_sizes, int n_in,
                              void* d_out, int out_size) {
    const int*   inputs = (const int*)  d_in[0];
    const float* hidden = (const float*)d_in[1];
    const float* cell   = (const float*)d_in[2];
    const float* emb    = (const float*)d_in[3];
    const float* Wx     = (const float*)d_in[4];
    const float* Wh     = (const float*)d_in[5];
    const float* bias   = (const float*)d_in[6];
    const float* Wout   = (const float*)d_in[7];
    const float* bout   = (const float*)d_in[8];
    float* out = (float*)d_out;

    float *pxz;
    __half *pA, *pB;
    __nv_bfloat16 *pA2, *pB2;
    cudaGetSymbolAddress((void**)&pxz, g_xz);
    cudaGetSymbolAddress((void**)&pA,  g_A);
    cudaGetSymbolAddress((void**)&pB,  g_B);
    cudaGetSymbolAddress((void**)&pA2, g_A2);
    cudaGetSymbolAddress((void**)&pB2, g_B2);

    cudaFuncSetAttribute(hmma_gemm<0>,
                         cudaFuncAttributeMaxDynamicSharedMemorySize, OSMEM);
    cudaFuncSetAttribute(hmma_gemm<1>,
                         cudaFuncAttributeMaxDynamicSharedMemorySize, OSMEM);
    cudaFuncSetAttribute(lstm_persistent,
                         cudaFuncAttributeMaxDynamicSharedMemorySize, L2SMEM);

    // 1. gather + split x -> A2 (bf16 3-term)
    split_x_kernel<<<(MM * XSEG + 255) / 256, 256>>>(inputs, emb);

    // 2. split + transpose W_x -> B2 (bf16 3-term)
    {
        dim3 grid(G4 / 32, XSEG / 32);   // (64, 10)
        split_wx_kernel<<<grid, dim3(32, 8)>>>(Wx);
    }

    // 3. init h (fp16 split pair)
    init_h_kernel<<<(BB * HH + 255) / 256, 256>>>(hidden);

    // 4. xz = A2 @ B2^T + b  (bf16 HMMA, 4096 x 2048 x 960)
    {
        dim3 grid(MM / OBM, G4 / OBN);   // (32, 16)
        hmma_gemm<0><<<grid, OTHREADS, OSMEM>>>((const uint16_t*)pA2,
                                                (const uint16_t*)pB2,
                                                bias, pxz, G4, XKK);
    }

    // 5. transpose W_out -> B (fp16)
    {
        dim3 grid(VV / 32, HH / 32);
        split_wout_kernel<<<grid, dim3(32, 8)>>>(Wout);
    }

    // 6. all 128 LSTM steps in ONE persistent launch (HMMA matvec)
    lstm_persistent<<<NCTA, 256, L2SMEM>>>(Wh, cell, out);

    // 7. logits = A @ B^T + b_out  (fp16 HMMA, 4096 x 32000 x 512)
    {
        dim3 grid(MM / OBM, VV / OBN);   // (32, 250)
        hmma_gemm<1><<<grid, OTHREADS, OSMEM>>>((const uint16_t*)pA,
                                                (const uint16_t*)pB,
                                                bout, out, VV, OKK);
    }
}

// round 17
// speedup vs baseline: 1.4613x; 1.0522x over previous
#include <cuda_runtime.h>
#include <cuda_bf16.h>
#include <cuda_fp16.h>
#include <math.h>
#include <cstdint>

#define BB 32
#define TT 128
#define VV 32000
#define EE 300
#define HH 512
#define G4 (4*HH)      // 2048
#define MM (BB*TT)     // 4096
#define LOGITS_ELEMS ((long long)MM * VV)   // 131072000

// out GEMM: plain fp16, K = 512
#define OKK 512
// xz GEMM: bf16 3-term stacked K
#define XSEG 320
#define XKK (3*XSEG)   // 960

// HMMA GEMM tiling (128x128, BK=64, 3 stages)
#define OBM 128
#define OBN 128
#define OBK 64
#define OSTAGES 3
#define OTHREADS 256
#define ROWB 144
#define A_ST_BYTES (128*ROWB)
#define B_ST_BYTES (128*ROWB)
#define STAGE_BYTES (A_ST_BYTES + B_ST_BYTES)  // 36864
#define OSMEM (OSTAGES*STAGE_BYTES)            // 110592

#define NTILE_M 32
#define NTILE_N 250
#define NTILES (NTILE_M*NTILE_N)               // 8000

// persistent LSTM (HMMA) — byte offsets in its dynamic smem region
#define NCTA 128
#define RSCALE 2048.0f
#define RINV   (1.0f/2048.0f)
#define SWH_OFF 0
#define SWH_ROWB 2064
#define SHH_OFF 33024
#define SH_ROWB 1040
#define SHL_OFF (SHH_OFF + 33280)
#define SZ_OFF  (SHL_OFF + 33280)
#define SC_OFF  (SZ_OFF + 16384)
#define L2SMEM  (SC_OFF + 512)                 // 116480
#define FUSED_SMEM (L2SMEM + OSMEM)            // 227072

// ---- scratch (device globals: allocation-free) ----
__device__ float g_xz[MM * G4];        // x @ W_x + b   [4096, 2048]
__device__ __half g_hh[2][BB * HH];    // h hi,  [b][u] fp16
__device__ __half g_hl[2][BB * HH];    // h lo * 2048, [b][u] fp16
__device__ __half g_A[(long long)MM * OKK];           // [t*32+bb][512] = Ah
__device__ __half g_B[(long long)VV * OKK];           // [32000,512]  = Bh
__device__ __nv_bfloat16 g_A2[(long long)MM * XKK];   // [4096,960]
__device__ __nv_bfloat16 g_B2[(long long)G4 * XKK];   // [2048,960]
__device__ unsigned g_bar_cnt = 0;
__device__ unsigned g_bar_gen = 0;
__device__ unsigned g_tile = 0;

// ===========================================================================
__device__ __forceinline__ uint32_t smem_u32(const void* p) {
    uint32_t a;
    asm("{ .reg .u64 t; cvta.to.shared.u64 t, %1; cvt.u32.u64 %0, t; }" : "=r"(a) : "l"(p));
    return a;
}
__device__ __forceinline__ void cp_async16(uint32_t s, const void* g) {
    asm volatile("cp.async.cg.shared.global [%0], [%1], 16;" :: "r"(s), "l"(g));
}
__device__ __forceinline__ void ldm_x4(uint32_t addr, uint32_t* r) {
    asm("ldmatrix.sync.aligned.m8n8.x4.shared.b16 {%0,%1,%2,%3}, [%4];"
        : "=r"(r[0]), "=r"(r[1]), "=r"(r[2]), "=r"(r[3]) : "r"(addr) : "memory");
}
__device__ __forceinline__ void mma_f16(float* d, const uint32_t* a,
                                        uint32_t b0, uint32_t b1) {
    asm("mma.sync.aligned.m16n8k16.row.col.f32.f16.f16.f32 "
        "{%0,%1,%2,%3}, {%4,%5,%6,%7}, {%8,%9}, {%0,%1,%2,%3};"
        : "+f"(d[0]), "+f"(d[1]), "+f"(d[2]), "+f"(d[3])
        : "r"(a[0]), "r"(a[1]), "r"(a[2]), "r"(a[3]), "r"(b0), "r"(b1));
}
#define BARX(id) asm volatile("bar.sync %0, %1;" :: "r"(id), "r"(256) : "memory")

// ---------------------------------------------------------------------------
// prep kernels
// ---------------------------------------------------------------------------
__global__ void split_x_kernel(const int* __restrict__ inputs,
                               const float* __restrict__ emb) {
    int i = blockIdx.x * blockDim.x + threadIdx.x;
    if (i < MM * XSEG) {
        int m = i / XSEG;
        int k = i - m * XSEG;
        float v = (k < EE) ? emb[(long long)inputs[m] * EE + k] : 0.f;
        __nv_bfloat16 hi = __float2bfloat16(v);
        __nv_bfloat16 lo = __float2bfloat16(v - __bfloat162float(hi));
        long long base = (long long)m * XKK;
        g_A2[base + k]            = hi;
        g_A2[base + XSEG + k]     = lo;
        g_A2[base + 2*XSEG + k]   = hi;
    }
}

__global__ void split_wx_kernel(const float* __restrict__ W) {
    __shared__ float t[32][33];
    int n0 = blockIdx.x * 32, k0 = blockIdx.y * 32;
    int tx = threadIdx.x, ty = threadIdx.y;           // 32 x 8
#pragma unroll
    for (int i = 0; i < 4; i++) {
        int k = k0 + ty + i * 8;
        t[ty + i * 8][tx] = (k < EE) ? W[(long long)k * G4 + n0 + tx] : 0.f;
    }
    __syncthreads();
#pragma unroll
    for (int i = 0; i < 4; i++) {
        int n = ty + i * 8;
        float v = t[tx][n];
        __nv_bfloat16 hi = __float2bfloat16(v);
        __nv_bfloat16 lo = __float2bfloat16(v - __bfloat162float(hi));
        long long base = (long long)(n0 + n) * XKK + k0;
        g_B2[base + tx]            = hi;
        g_B2[base + XSEG + tx]     = hi;
        g_B2[base + 2*XSEG + tx]   = lo;
    }
}

__global__ void split_wout_kernel(const float* __restrict__ W) {
    __shared__ float t[32][33];
    int n0 = blockIdx.x * 32, k0 = blockIdx.y * 32;
    int tx = threadIdx.x, ty = threadIdx.y;   // 32 x 8
#pragma unroll
    for (int i = 0; i < 4; i++) {
        int k = ty + i * 8;
        t[k][tx] = W[(long long)(k0 + k) * VV + n0 + tx];
    }
    __syncthreads();
#pragma unroll
    for (int i = 0; i < 4; i++) {
        int n = ty + i * 8;
        g_B[(long long)(n0 + n) * OKK + k0 + tx] = __float2half(t[tx][n]);
    }
}

__global__ void init_h_kernel(const float* __restrict__ hidden) {
    int i = blockIdx.x * blockDim.x + threadIdx.x;
    if (i == 0) g_tile = 0;
    if (i < BB * HH) {
        float v = hidden[i];
        __half hh = __float2half(v);
        g_hh[0][i] = hh;
        g_hl[0][i] = __float2half((v - __half2float(hh)) * RSCALE);
    }
}

// ---------------------------------------------------------------------------
// Generic HMMA 16-bit GEMM (standalone; used for xz only)
// ---------------------------------------------------------------------------
template<int FP16M>
__global__ void __launch_bounds__(OTHREADS, 2)
hmma_gemm(const uint16_t* __restrict__ A, const uint16_t* __restrict__ B,
          const float* __restrict__ bias, float* __restrict__ C,
          int N, int K) {
    extern __shared__ char smem[];
    const int tid  = threadIdx.x;
    const int lane = tid & 31;
    const int wid  = tid >> 5;
    const int wm   = wid & 3;
    const int wn   = wid >> 2;
    const int m0 = blockIdx.x * OBM;
    const int n0 = blockIdx.y * OBN;
    const uint32_t sbase = smem_u32(smem);

    auto load_stage = [&](int s, int kt) {
        uint32_t sA = sbase + s * STAGE_BYTES;
        uint32_t sB = sA + A_ST_BYTES;
        long long k0 = (long long)kt * OBK;
#pragma unroll
        for (int i = 0; i < 4; i++) {
            int idx = tid + i * 256;
            int r = idx >> 3, ch = idx & 7;
            cp_async16(sA + r * ROWB + ch * 16,
                       A + (long long)(m0 + r) * K + k0 + ch * 8);
        }
#pragma unroll
        for (int i = 0; i < 4; i++) {
            int idx = tid + i * 256;
            int r = idx >> 3, ch = idx & 7;
            cp_async16(sB + r * ROWB + ch * 16,
                       B + (long long)(n0 + r) * K + k0 + ch * 8);
        }
        asm volatile("cp.async.commit_group;" ::: "memory");
    };

    float acc[2][8][4];
#pragma unroll
    for (int i = 0; i < 2; i++)
#pragma unroll
        for (int j = 0; j < 8; j++)
#pragma unroll
            for (int q = 0; q < 4; q++) acc[i][j][q] = 0.f;

    const int KT = K / OBK;
#pragma unroll
    for (int s = 0; s < OSTAGES - 1; s++)
        if (s < KT) load_stage(s, s);

    for (int kt = 0; kt < KT; kt++) {
        asm volatile("cp.async.wait_group %0;" :: "n"(OSTAGES - 2));
        __syncthreads();
        if (kt + OSTAGES - 1 < KT)
            load_stage((kt + OSTAGES - 1) % OSTAGES, kt + OSTAGES - 1);

        uint32_t sA = sbase + (kt % OSTAGES) * STAGE_BYTES;
        uint32_t sB = sA + A_ST_BYTES;
        const int krow = lane & 15;
#pragma unroll
        for (int ks = 0; ks < 4; ks++) {
            const int kcolb = (ks * 16 + (lane >> 4) * 8) * 2;
            uint32_t a[2][4], bb[4][4];
#pragma unroll
            for (int mt = 0; mt < 2; mt++)
                ldm_x4(sA + (wm * 32 + mt * 16 + krow) * ROWB + kcolb, a[mt]);
#pragma unroll
            for (int np = 0; np < 4; np++)
                ldm_x4(sB + (wn * 64 + np * 16 + krow) * ROWB + kcolb, bb[np]);
#pragma unroll
            for (int mt = 0; mt < 2; mt++)
#pragma unroll
                for (int nt = 0; nt < 8; nt++) {
                    uint32_t b0 = bb[nt >> 1][nt & 1];
                    uint32_t b1 = bb[nt >> 1][(nt & 1) + 2];
                    if (FP16M) {
                        mma_f16(acc[mt][nt], a[mt], b0, b1);
                    } else {
                        asm("mma.sync.aligned.m16n8k16.row.col.f32.bf16.bf16.f32 "
                            "{%0,%1,%2,%3}, {%4,%5,%6,%7}, {%8,%9}, {%0,%1,%2,%3};"
                            : "+f"(acc[mt][nt][0]), "+f"(acc[mt][nt][1]),
                              "+f"(acc[mt][nt][2]), "+f"(acc[mt][nt][3])
                            : "r"(a[mt][0]), "r"(a[mt][1]), "r"(a[mt][2]), "r"(a[mt][3]),
                              "r"(b0), "r"(b1));
                    }
                }
        }
    }

    const int row_b = m0 + wm * 32 + (lane >> 2);
    const int col_b = n0 + wn * 64 + (lane & 3) * 2;
#pragma unroll
    for (int nt = 0; nt < 8; nt++) {
        int col = col_b + nt * 8;
        float b0v = __ldg(bias + col);
        float b1v = __ldg(bias + col + 1);
#pragma unroll
        for (int mt = 0; mt < 2; mt++) {
            long long r0 = row_b + mt * 16;
            float2 v0 = make_float2(acc[mt][nt][0] + b0v, acc[mt][nt][1] + b1v);
            float2 v1 = make_float2(acc[mt][nt][2] + b0v, acc[mt][nt][3] + b1v);
            *(float2*)&C[r0 * N + col]       = v0;
            *(float2*)&C[(r0 + 8) * N + col] = v1;
        }
    }
}

// ---------------------------------------------------------------------------
// GEMM worker: work-steals 128x128 tiles of logits = A @ B^T + bout.
// A rows ordered m = t*32 + bb; tile mj needs g_bar_gen - gen0 >= 4*mj+4.
// Output row remap: m -> (bb*128 + t).
// ---------------------------------------------------------------------------
__device__ void gemm_worker(int tid2, char* gsm, int barid,
                            const float* __restrict__ bout,
                            float* __restrict__ out,
                            unsigned gen0, unsigned* s_tile) {
    const int lane = tid2 & 31;
    const int wid  = tid2 >> 5;        // 0..7
    const int wm   = wid & 3;
    const int wn   = wid >> 2;
    const uint32_t sbase = smem_u32(gsm);
    const __half* __restrict__ A = g_A;
    const __half* __restrict__ B = g_B;

    for (;;) {
        if (tid2 == 0) *s_tile = atomicAdd(&g_tile, 1u);
        BARX(barid);
        unsigned j = *s_tile;
        if (j >= NTILES) return;
        const int mj = (int)(j / NTILE_N);
        const int nj = (int)(j % NTILE_N);
        const int m0 = mj * OBM;
        const int n0 = nj * OBN;

        if (tid2 == 0) {
            while (*(volatile unsigned*)&g_bar_gen - gen0 < (unsigned)(mj * 4 + 4)) { }
        }
        BARX(barid);

        auto load_stage = [&](int s, int kt) {
            uint32_t sA = sbase + s * STAGE_BYTES;
            uint32_t sB = sA + A_ST_BYTES;
            long long k0 = (long long)kt * OBK;
#pragma unroll
            for (int i = 0; i < 4; i++) {
                int idx = tid2 + i * 256;
                int r = idx >> 3, ch = idx & 7;
                cp_async16(sA + r * ROWB + ch * 16,
                           A + (long long)(m0 + r) * OKK + k0 + ch * 8);
            }
#pragma unroll
            for (int i = 0; i < 4; i++) {
                int idx = tid2 + i * 256;
                int r = idx >> 3, ch = idx & 7;
                cp_async16(sB + r * ROWB + ch * 16,
                           B + (long long)(n0 + r) * OKK + k0 + ch * 8);
            }
            asm volatile("cp.async.commit_group;" ::: "memory");
        };

        float acc[2][8][4];
#pragma unroll
        for (int i = 0; i < 2; i++)
#pragma unroll
            for (int jj = 0; jj < 8; jj++)
#pragma unroll
                for (int q = 0; q < 4; q++) acc[i][jj][q] = 0.f;

        const int KT = OKK / OBK;   // 8
#pragma unroll
        for (int s = 0; s < OSTAGES - 1; s++) load_stage(s, s);

        for (int kt = 0; kt < KT; kt++) {
            asm volatile("cp.async.wait_group %0;" :: "n"(OSTAGES - 2));
            BARX(barid);
            if (kt + OSTAGES - 1 < KT)
                load_stage((kt + OSTAGES - 1) % OSTAGES, kt + OSTAGES - 1);

            uint32_t sA = sbase + (kt % OSTAGES) * STAGE_BYTES;
            uint32_t sB = sA + A_ST_BYTES;
            const int krow = lane & 15;
#pragma unroll
            for (int ks = 0; ks < 4; ks++) {
                const int kcolb = (ks * 16 + (lane >> 4) * 8) * 2;
                uint32_t a[2][4], bb[4][4];
#pragma unroll
                for (int mt = 0; mt < 2; mt++)
                    ldm_x4(sA + (wm * 32 + mt * 16 + krow) * ROWB + kcolb, a[mt]);
#pragma unroll
                for (int np = 0; np < 4; np++)
                    ldm_x4(sB + (wn * 64 + np * 16 + krow) * ROWB + kcolb, bb[np]);
#pragma unroll
                for (int mt = 0; mt < 2; mt++)
#pragma unroll
                    for (int nt = 0; nt < 8; nt++) {
                        uint32_t b0 = bb[nt >> 1][nt & 1];
                        uint32_t b1 = bb[nt >> 1][(nt & 1) + 2];
                        mma_f16(acc[mt][nt], a[mt], b0, b1);
                    }
            }
            BARX(barid);   // protect stage reuse (wait_group is per-thread)
        }

        const int row_b = m0 + wm * 32 + (lane >> 2);
        const int col_b = n0 + wn * 64 + (lane & 3) * 2;
#pragma unroll
        for (int nt = 0; nt < 8; nt++) {
            int col = col_b + nt * 8;
            float b0v = __ldg(bout + col);
            float b1v = __ldg(bout + col + 1);
#pragma unroll
            for (int mt = 0; mt < 2; mt++) {
                int r0 = row_b + mt * 16;
                long long o0 = (long long)((r0 & 31) * TT + (r0 >> 5)) * VV;
                long long o1 = (long long)(((r0 + 8) & 31) * TT + ((r0 + 8) >> 5)) * VV;
                float2 v0 = make_float2(acc[mt][nt][0] + b0v, acc[mt][nt][1] + b1v);
                float2 v1 = make_float2(acc[mt][nt][2] + b0v, acc[mt][nt][3] + b1v);
                *(float2*)&out[o0 + col] = v0;
                *(float2*)&out[o1 + col] = v1;
            }
        }
    }
}

// ---------------------------------------------------------------------------
// LSTM role (R14 body, named barrier 1, A-layout m = t*32+bb)
// ---------------------------------------------------------------------------
__device__ void lstm_role(char* smem, int tid, unsigned gen0,
                          const float* __restrict__ Wh,
                          const float* __restrict__ cell,
                          float* __restrict__ out) {
    float* sz = (float*)(smem + SZ_OFF);
    float* sc = (float*)(smem + SC_OFF);
    const uint32_t sbase = smem_u32(smem);
    const int lane = tid & 31;
    const int kg = tid >> 5;
    const int u0 = blockIdx.x * 4;

    // one-time: Wh slice -> fp16 2-term in smem
#pragma unroll
    for (int it = 0; it < 32; it++) {
        int e = tid + it * 256;
        int k = e >> 4, c = e & 15;
        int uu = c >> 2, g = c & 3;
        float w = Wh[(long long)k * G4 + g * HH + u0 + uu];
        __half wh = __float2half(w);
        __half wl = __float2half((w - __half2float(wh)) * RSCALE);
        *(__half*)(smem + SWH_OFF + c * SWH_ROWB + k * 2)         = wh;
        *(__half*)(smem + SWH_OFF + c * SWH_ROWB + (512 + k) * 2) = wl;
    }
    if (tid < 128) sc[tid] = cell[(tid & 31) * HH + u0 + (tid >> 5)];
    BARX(1);

    for (int t = 0; t < TT; t++) {
        const __half* __restrict__ srch = g_hh[t & 1];
        const __half* __restrict__ srcl = g_hl[t & 1];

#pragma unroll
        for (int j = 0; j < 8; j++) {
            int e = lane + j * 32;
            int b = e >> 3, ch = e & 7;
            cp_async16(sbase + SHH_OFF + b * SH_ROWB + kg * 128 + ch * 16,
                       srch + b * HH + kg * 64 + ch * 8);
            cp_async16(sbase + SHL_OFF + b * SH_ROWB + kg * 128 + ch * 16,
                       srcl + b * HH + kg * 64 + ch * 8);
        }
        asm volatile("cp.async.commit_group;" ::: "memory");

        // early xz prefetch
        float xzv[4];
        if (tid < 128) {
            int bb = tid & 31, uu = tid >> 5;
            const float* xzr = g_xz + (long long)(bb * TT + t) * G4 + u0 + uu;
            xzv[0] = __ldg(xzr);
            xzv[1] = __ldg(xzr + HH);
            xzv[2] = __ldg(xzr + 2 * HH);
            xzv[3] = __ldg(xzr + 3 * HH);
        }

        asm volatile("cp.async.wait_group 0;" ::: "memory");
        __syncwarp();

        float accA[2][2][4], accB[2][2][4];
#pragma unroll
        for (int i = 0; i < 2; i++)
#pragma unroll
            for (int j = 0; j < 2; j++)
#pragma unroll
                for (int q = 0; q < 4; q++) { accA[i][j][q] = 0.f; accB[i][j][q] = 0.f; }

        const int krow = lane & 15;
        const int kgrp = (lane >> 4) * 8;
#pragma unroll
        for (int seg = 0; seg < 3; seg++) {
            const uint32_t Abase = sbase + ((seg == 1) ? SHL_OFF : SHH_OFF);
            const uint32_t Bkoff = (seg == 2) ? 512u : 0u;
            float (*acc)[2][4] = (seg == 0) ? accA : accB;
#pragma unroll
            for (int ki = 0; ki < 4; ki++) {
                const int kcol = kg * 64 + ki * 16;
                uint32_t a[2][4], bb[4];
#pragma unroll
                for (int mt = 0; mt < 2; mt++)
                    ldm_x4(Abase + (mt * 16 + krow) * SH_ROWB + (kcol + kgrp) * 2, a[mt]);
                ldm_x4(sbase + SWH_OFF + krow * SWH_ROWB + (Bkoff + kcol + kgrp) * 2, bb);
#pragma unroll
                for (int mt = 0; mt < 2; mt++)
#pragma unroll
                    for (int nt = 0; nt < 2; nt++)
                        mma_f16(acc[mt][nt], a[mt], bb[nt], bb[nt + 2]);
            }
        }

        {
            float* zb = sz + kg * 512;
#pragma unroll
            for (int mt = 0; mt < 2; mt++)
#pragma unroll
                for (int nt = 0; nt < 2; nt++)
#pragma unroll
                    for (int q = 0; q < 4; q++) {
                        int b = mt * 16 + (lane >> 2) + ((q >> 1) * 8);
                        int c = nt * 8 + (lane & 3) * 2 + (q & 1);
                        zb[c * 32 + b] = accA[mt][nt][q] + accB[mt][nt][q] * RINV;
                    }
        }
        BARX(1);

        if (tid < 128) {
            int bb = tid & 31, uu = tid >> 5;
            float z[4];
#pragma unroll
            for (int g = 0; g < 4; g++) {
                int c = uu * 4 + g;
                float s = 0.f;
#pragma unroll
                for (int q = 0; q < 8; q++) s += sz[q * 512 + c * 32 + bb];
                z[g] = s;
            }
            float zi = z[0] + xzv[0];
            float zf = z[1] + xzv[1];
            float zg = z[2] + xzv[2];
            float zo = z[3] + xzv[3];
            float si = 1.f / (1.f + expf(-zi));
            float sf = 1.f / (1.f + expf(-zf));
            float so = 1.f / (1.f + expf(-zo));
            float cn = sf * sc[tid] + si * tanhf(zg);
            float hn = so * tanhf(cn);
            sc[tid] = cn;
            __half hh = __float2half(hn);
            __half hl = __float2half((hn - __half2float(hh)) * RSCALE);
            int hidx = bb * HH + u0 + uu;
            g_hh[(t + 1) & 1][hidx] = hh;
            g_hl[(t + 1) & 1][hidx] = hl;
            g_A[(long long)(t * BB + bb) * OKK + u0 + uu] = hh;   // m = t*32+bb
            if (t == TT - 1)
                out[LOGITS_ELEMS + hidx] = hn;
        }

        BARX(1);
        if (tid == 0) {
            __threadfence();
            if (atomicAdd(&g_bar_cnt, 1u) == NCTA - 1) {
                *(volatile unsigned*)&g_bar_cnt = 0;
                __threadfence();
                atomicAdd(&g_bar_gen, 1u);
            } else {
                while (*(volatile unsigned*)&g_bar_gen - gen0 < (unsigned)(t + 1)) { }
            }
            __threadfence();
        }
        BARX(1);
    }

    if (tid < 128) {
        out[LOGITS_ELEMS + BB * HH + (tid & 31) * HH + u0 + (tid >> 5)] = sc[tid];
    }
    BARX(1);
}

// ---------------------------------------------------------------------------
// Fused persistent kernel: warps 0-7 LSTM (then join GEMM), warps 8-15 GEMM
// ---------------------------------------------------------------------------
__global__ void __launch_bounds__(512, 1)
lstm_fused(const float* __restrict__ Wh, const float* __restrict__ cell,
           const float* __restrict__ bout, float* __restrict__ out) {
    extern __shared__ char smem[];
    __shared__ unsigned s_gen0;
    __shared__ unsigned s_tile[2];
    const int tid = threadIdx.x;
    if (tid == 0) s_gen0 = *(volatile unsigned*)&g_bar_gen;
    __syncthreads();
    const unsigned gen0 = s_gen0;

    if (tid < 256) {
        lstm_role(smem, tid, gen0, Wh, cell, out);
        gemm_worker(tid, smem, 1, bout, out, gen0, &s_tile[0]);
    } else {
        gemm_worker(tid - 256, smem + L2SMEM, 2, bout, out, gen0, &s_tile[1]);
    }
}

// ---------------------------------------------------------------------------
extern "C" void kernel_launch(void* const* d_in, const int* in_sizes, int n_in,
                              void* d_out, int out_size) {
    const int*   inputs = (const int*)  d_in[0];
    const float* hidden = (const float*)d_in[1];
    const float* cell   = (const float*)d_in[2];
    const float* emb    = (const float*)d_in[3];
    const float* Wx     = (const float*)d_in[4];
    const float* Wh     = (const float*)d_in[5];
    const float* bias   = (const float*)d_in[6];
    const float* Wout   = (const float*)d_in[7];
    const float* bout   = (const float*)d_in[8];
    float* out = (float*)d_out;

    float *pxz;
    __nv_bfloat16 *pA2, *pB2;
    cudaGetSymbolAddress((void**)&pxz, g_xz);
    cudaGetSymbolAddress((void**)&pA2, g_A2);
    cudaGetSymbolAddress((void**)&pB2, g_B2);

    cudaFuncSetAttribute(hmma_gemm<0>,
                         cudaFuncAttributeMaxDynamicSharedMemorySize, OSMEM);
    cudaFuncSetAttribute(lstm_fused,
                         cudaFuncAttributeMaxDynamicSharedMemorySize, FUSED_SMEM);

    // 1. gather + split x -> A2 (bf16 3-term)
    split_x_kernel<<<(MM * XSEG + 255) / 256, 256>>>(inputs, emb);

    // 2. split + transpose W_x -> B2 (bf16 3-term)
    {
        dim3 grid(G4 / 32, XSEG / 32);   // (64, 10)
        split_wx_kernel<<<grid, dim3(32, 8)>>>(Wx);
    }

    // 3. init h (fp16 split pair) + reset tile counter
    init_h_kernel<<<(BB * HH + 255) / 256, 256>>>(hidden);

    // 4. xz = A2 @ B2^T + b  (bf16 HMMA, 4096 x 2048 x 960)
    {
        dim3 grid(MM / OBM, G4 / OBN);   // (32, 16)
        hmma_gemm<0><<<grid, OTHREADS, OSMEM>>>((const uint16_t*)pA2,
                                                (const uint16_t*)pB2,
                                                bias, pxz, G4, XKK);
    }

    // 5. transpose W_out -> B (fp16)
    {
        dim3 grid(VV / 32, HH / 32);
        split_wout_kernel<<<grid, dim3(32, 8)>>>(Wout);
    }

    // 6. fused: LSTM (warps 0-7) + overlapped logits GEMM (warps 8-15,
    //    joined by warps 0-7 after the recurrence finishes)
    lstm_fused<<<NCTA, 512, FUSED_SMEM>>>(Wh, cell, bout, out);
}